// round 2
// baseline (speedup 1.0000x reference)
#include <cuda_runtime.h>

// YOLOv1 loss — one block per image, coalesced smem-staged sweep.
// S=7, B=2, C=20, D=30, CELL=64, IMG=448, LAMBDA_COORD=5, LAMBDA_NOOBJ=0.5

#define D_FEAT 30
#define S_GRID 7
#define GBOX 8
#define CELLS_PER_IMG 49          // 7*7
#define FLOATS_PER_IMG 1470       // 49*30
#define F2_PER_IMG 735            // 1470/2
#define THREADS 128

__global__ void init_out(float* out) { out[0] = 0.0f; }

__global__ void __launch_bounds__(THREADS) yolo_loss_kernel(
    const float*  __restrict__ feat,
    const float2* __restrict__ feat2,
    const float*  __restrict__ bboxes,
    const int*    __restrict__ labels,
    float* __restrict__ out)
{
    const float CELL = 64.0f;
    const float INV_CELL = 1.0f / 64.0f;
    const float IMG = 448.0f;
    const float INV_IMG = 1.0f / 448.0f;

    const int n = blockIdx.x;
    const int tid = threadIdx.x;

    __shared__ float sm[FLOATS_PER_IMG];

    float acc = 0.0f;

    // ---- Coalesced load of this image's featmap (float2), with on-the-fly
    //      noobj accumulation: 0.5 * conf^2 for elements e where e%30 ∈ {4,9}.
    const float2* src = feat2 + (size_t)n * F2_PER_IMG;
    #pragma unroll
    for (int j = tid; j < F2_PER_IMG; j += THREADS) {
        const float2 v = __ldg(src + j);
        const int e0 = 2 * j;
        const int r0 = e0 % D_FEAT;        // even
        // e0 even -> r0 even; conf indices within row are 4 (even) and 9 (odd).
        if (r0 == 4) acc = fmaf(0.5f * v.x, v.x, acc);
        if (r0 == 8) acc = fmaf(0.5f * v.y, v.y, acc);   // e0+1 has r==9
        sm[e0]     = v.x;
        sm[e0 + 1] = v.y;
    }
    __syncthreads();

    // ---- 8 ground-truth boxes, one per thread (threads 0..7)
    if (tid < GBOX) {
        const int i = n * GBOX + tid;
        const float4 bb = __ldg((const float4*)(bboxes + (size_t)i * 4));
        const float x1 = bb.x, y1 = bb.y, x2 = bb.z, y2 = bb.w;

        const float cx = 0.5f * (x1 + x2);
        const float cy = 0.5f * (y1 + y2);
        const float gw = x2 - x1;
        const float gh = y2 - y1;

        int col = (int)floorf(cx * INV_CELL);
        int row = (int)floorf(cy * INV_CELL);
        col = min(S_GRID - 1, max(0, col));
        row = min(S_GRID - 1, max(0, row));

        const float* cell = sm + (row * S_GRID + col) * D_FEAT;

        const float gx0 = (float)col * CELL;
        const float gy0 = (float)row * CELL;
        const float tx = cx * INV_CELL - (float)col;
        const float ty = cy * INV_CELL - (float)row;
        const float stw = sqrtf(gw * INV_IMG);
        const float sth = sqrtf(gh * INV_IMG);
        const float a2 = fmaxf(gw, 0.0f) * fmaxf(gh, 0.0f);

        float px[2], py[2], pw[2], ph[2], pc[2], iou[2];
        #pragma unroll
        for (int b = 0; b < 2; b++) {
            px[b] = cell[b * 5 + 0];
            py[b] = cell[b * 5 + 1];
            pw[b] = cell[b * 5 + 2];
            ph[b] = cell[b * 5 + 3];
            pc[b] = cell[b * 5 + 4];

            const float pcx = gx0 + px[b] * CELL;
            const float pcy = gy0 + py[b] * CELL;
            const float pwa = pw[b] * IMG;
            const float pha = ph[b] * IMG;
            const float bx1 = pcx - 0.5f * pwa;
            const float by1 = pcy - 0.5f * pha;
            const float bx2 = pcx + 0.5f * pwa;
            const float by2 = pcy + 0.5f * pha;

            const float ix1 = fmaxf(bx1, x1);
            const float iy1 = fmaxf(by1, y1);
            const float ix2 = fminf(bx2, x2);
            const float iy2 = fminf(by2, y2);
            const float inter = fmaxf(ix2 - ix1, 0.0f) * fmaxf(iy2 - iy1, 0.0f);
            const float a1 = fmaxf(bx2 - bx1, 0.0f) * fmaxf(by2 - by1, 0.0f);
            iou[b] = inter / (a1 + a2 - inter + 1e-6f);
        }

        // argmax over 2 boxes; first wins ties (jnp.argmax semantics)
        const int bi = (iou[1] > iou[0]) ? 1 : 0;

        // coord loss (LAMBDA_COORD = 5)
        const float dpx = px[bi] - tx;
        const float dpy = py[bi] - ty;
        const float dsw = sqrtf(fmaxf(pw[bi], 0.0f)) - stw;
        const float dsh = sqrtf(fmaxf(ph[bi], 0.0f)) - sth;
        acc += 5.0f * (dpx * dpx + dpy * dpy + dsw * dsw + dsh * dsh);

        // conf_obj
        const float dc = pc[bi] - iou[bi];
        acc = fmaf(dc, dc, acc);

        // noobj correction: subtract 0.5 * resp * pc^2
        acc = fmaf(-0.5f * pc[bi], pc[bi], acc);

        // class loss: sum(clsp^2) - 2*clsp[label] + 1
        const int lab = __ldg(labels + i);
        float cls = 1.0f;
        #pragma unroll
        for (int c = 0; c < 20; c++) {
            const float v = cell[10 + c];
            cls = fmaf(v, v, cls);
        }
        cls -= 2.0f * cell[10 + lab];
        acc += cls;
    }

    // ---- Block reduction, one atomicAdd per block
    __shared__ float red[4];
    const int lane = tid & 31;
    const int wid = tid >> 5;
    #pragma unroll
    for (int off = 16; off > 0; off >>= 1)
        acc += __shfl_down_sync(0xFFFFFFFFu, acc, off);
    if (lane == 0) red[wid] = acc;
    __syncthreads();
    if (wid == 0) {
        float v = (lane < 4) ? red[lane] : 0.0f;
        #pragma unroll
        for (int off = 2; off > 0; off >>= 1)
            v += __shfl_down_sync(0xFFFFFFFFu, v, off);
        if (lane == 0) atomicAdd(out, v);
    }
}

extern "C" void kernel_launch(void* const* d_in, const int* in_sizes, int n_in,
                              void* d_out, int out_size) {
    const float* feat   = (const float*)d_in[0];
    const float* bboxes = (const float*)d_in[1];
    const int*   labels = (const int*)d_in[2];
    float* out = (float*)d_out;

    const int N = in_sizes[0] / FLOATS_PER_IMG;  // 16384

    init_out<<<1, 1>>>(out);
    yolo_loss_kernel<<<N, THREADS>>>(feat, (const float2*)feat, bboxes, labels, out);
}

// round 3
// speedup vs baseline: 1.3811x; 1.3811x over previous
#include <cuda_runtime.h>

// YOLOv1 loss — fused: coalesced float4 full sweep (noobj) + per-(n,g) gather.
// S=7, B=2, C=20, D=30, CELL=64, IMG=448, LAMBDA_COORD=5, LAMBDA_NOOBJ=0.5

#define D_FEAT 30
#define S_GRID 7
#define GBOX 8
#define THREADS 256
#define NBLOCKS 1185   // divisible by 15 -> grid stride % 15 == 0

__global__ void init_out(float* out) { out[0] = 0.0f; }

__global__ void __launch_bounds__(THREADS) yolo_loss_kernel(
    const float*  __restrict__ feat,
    const float4* __restrict__ feat4,
    const float*  __restrict__ bboxes,
    const int*    __restrict__ labels,
    float* __restrict__ out,
    int n4,       // total float4 count = N*1470/4
    int M)        // N * GBOX
{
    const float CELL = 64.0f;
    const float INV_CELL = 1.0f / 64.0f;
    const float IMG = 448.0f;
    const float INV_IMG = 1.0f / 448.0f;

    const int tid = blockIdx.x * blockDim.x + threadIdx.x;
    const int nth = gridDim.x * blockDim.x;   // ≡ 0 (mod 15)

    float acc = 0.0f;

    // ---- Part 1: noobj base: 0.5 * sum over all cells of (conf0^2 + conf1^2).
    // Flat element index e = 4*j. Row-local index r = e % 30 = (4*j) % 30,
    // determined by m = j % 15 (loop-invariant since nth % 15 == 0):
    //   m==1 -> r=4  -> conf at .x     m==2 -> r=8  -> conf at .y (e+1: 9)
    //   m==8 -> r=2  -> conf at .z (4) m==9 -> r=6  -> conf at .w (9)
    const int m = tid % 15;
    #pragma unroll 4
    for (int j = tid; j < n4; j += nth) {
        const float4 v = __ldg(feat4 + j);
        const float c = (m == 1) ? v.x : (m == 2) ? v.y
                      : (m == 8) ? v.z : (m == 9) ? v.w : 0.0f;
        acc = fmaf(0.5f * c, c, acc);
    }

    // ---- Part 2: per (n, g) terms (rows now resident in L2)
    for (int i = tid; i < M; i += nth) {
        const int n = i >> 3;
        const float4 bb = __ldg((const float4*)(bboxes + (size_t)i * 4));
        const float x1 = bb.x, y1 = bb.y, x2 = bb.z, y2 = bb.w;

        const float cx = 0.5f * (x1 + x2);
        const float cy = 0.5f * (y1 + y2);
        const float gw = x2 - x1;
        const float gh = y2 - y1;

        int col = (int)floorf(cx * INV_CELL);
        int row = (int)floorf(cy * INV_CELL);
        col = min(S_GRID - 1, max(0, col));
        row = min(S_GRID - 1, max(0, row));

        const float* cell = feat + ((size_t)n * (S_GRID * S_GRID) + row * S_GRID + col) * D_FEAT;
        const float2* cell2 = (const float2*)cell;   // 120B row base: 8B aligned

        // whole row as 15 float2s (L2 hits)
        float2 r2[15];
        #pragma unroll
        for (int k = 0; k < 15; k++) r2[k] = __ldg(cell2 + k);

        const float px0 = r2[0].x, py0 = r2[0].y;
        const float pw0 = r2[1].x, ph0 = r2[1].y;
        const float pc0 = r2[2].x;
        const float px1 = r2[2].y, py1 = r2[3].x;
        const float pw1 = r2[3].y, ph1 = r2[4].x;
        const float pc1 = r2[4].y;

        const float gx0 = (float)col * CELL;
        const float gy0 = (float)row * CELL;
        const float tx = cx * INV_CELL - (float)col;
        const float ty = cy * INV_CELL - (float)row;
        const float stw = sqrtf(gw * INV_IMG);
        const float sth = sqrtf(gh * INV_IMG);
        const float a2 = fmaxf(gw, 0.0f) * fmaxf(gh, 0.0f);

        float px[2] = {px0, px1}, py[2] = {py0, py1};
        float pw[2] = {pw0, pw1}, ph[2] = {ph0, ph1};
        float pc[2] = {pc0, pc1}, iou[2];
        #pragma unroll
        for (int b = 0; b < 2; b++) {
            const float pcx = gx0 + px[b] * CELL;
            const float pcy = gy0 + py[b] * CELL;
            const float pwa = pw[b] * IMG;
            const float pha = ph[b] * IMG;
            const float bx1 = pcx - 0.5f * pwa;
            const float by1 = pcy - 0.5f * pha;
            const float bx2 = pcx + 0.5f * pwa;
            const float by2 = pcy + 0.5f * pha;

            const float ix1 = fmaxf(bx1, x1);
            const float iy1 = fmaxf(by1, y1);
            const float ix2 = fminf(bx2, x2);
            const float iy2 = fminf(by2, y2);
            const float inter = fmaxf(ix2 - ix1, 0.0f) * fmaxf(iy2 - iy1, 0.0f);
            const float a1 = fmaxf(bx2 - bx1, 0.0f) * fmaxf(by2 - by1, 0.0f);
            iou[b] = inter / (a1 + a2 - inter + 1e-6f);
        }

        // argmax over 2 boxes; first wins ties (jnp.argmax semantics)
        const int bi = (iou[1] > iou[0]) ? 1 : 0;

        // coord loss (LAMBDA_COORD = 5)
        const float dpx = px[bi] - tx;
        const float dpy = py[bi] - ty;
        const float dsw = sqrtf(fmaxf(pw[bi], 0.0f)) - stw;
        const float dsh = sqrtf(fmaxf(ph[bi], 0.0f)) - sth;
        acc += 5.0f * (dpx * dpx + dpy * dpy + dsw * dsw + dsh * dsh);

        // conf_obj
        const float dc = pc[bi] - iou[bi];
        acc = fmaf(dc, dc, acc);

        // noobj correction: subtract 0.5 * resp * pc^2
        acc = fmaf(-0.5f * pc[bi], pc[bi], acc);

        // class loss: sum(clsp^2) - 2*clsp[label] + 1
        const int lab = __ldg(labels + i);
        float cls = 1.0f;
        #pragma unroll
        for (int k = 5; k < 15; k++) {
            cls = fmaf(r2[k].x, r2[k].x, cls);
            cls = fmaf(r2[k].y, r2[k].y, cls);
        }
        const int kq = lab >> 1;
        float labv = 0.0f;
        #pragma unroll
        for (int k = 0; k < 10; k++)
            if (k == kq) labv = (lab & 1) ? r2[5 + k].y : r2[5 + k].x;
        cls -= 2.0f * labv;
        acc += cls;
    }

    // ---- Block reduction, one atomicAdd per block
    __shared__ float red[8];
    const int lane = threadIdx.x & 31;
    const int wid = threadIdx.x >> 5;
    #pragma unroll
    for (int off = 16; off > 0; off >>= 1)
        acc += __shfl_down_sync(0xFFFFFFFFu, acc, off);
    if (lane == 0) red[wid] = acc;
    __syncthreads();
    if (wid == 0) {
        float v = (lane < (THREADS >> 5)) ? red[lane] : 0.0f;
        #pragma unroll
        for (int off = 4; off > 0; off >>= 1)
            v += __shfl_down_sync(0xFFFFFFFFu, v, off);
        if (lane == 0) atomicAdd(out, v);
    }
}

extern "C" void kernel_launch(void* const* d_in, const int* in_sizes, int n_in,
                              void* d_out, int out_size) {
    const float* feat   = (const float*)d_in[0];
    const float* bboxes = (const float*)d_in[1];
    const int*   labels = (const int*)d_in[2];
    float* out = (float*)d_out;

    const int total = in_sizes[0];                       // N * 1470
    const int n4 = total / 4;
    const int N = total / (S_GRID * S_GRID * D_FEAT);    // 16384
    const int M = N * GBOX;

    init_out<<<1, 1>>>(out);
    yolo_loss_kernel<<<NBLOCKS, THREADS>>>(feat, (const float4*)feat,
                                           bboxes, labels, out, n4, M);
}

// round 4
// speedup vs baseline: 2.0716x; 1.5000x over previous
#include <cuda_runtime.h>

// YOLOv1 loss — single fused kernel, block-role partition:
//   blocks [0, GATHER_BLOCKS): per-(n,g) gather terms (latency-bound)
//   blocks [GATHER_BLOCKS, +SWEEP_BLOCKS): coalesced float4 noobj sweep (BW-bound)
// S=7, B=2, C=20, D=30, CELL=64, IMG=448, LAMBDA_COORD=5, LAMBDA_NOOBJ=0.5

#define D_FEAT 30
#define S_GRID 7
#define GBOX 8
#define THREADS 256
#define GATHER_BLOCKS 512          // 512*256 = 131072 = N*GBOX exactly
#define SWEEP_BLOCKS 1920          // divisible by 15 -> sweep stride % 15 == 0

__global__ void init_out(float* out) { out[0] = 0.0f; }

__global__ void __launch_bounds__(THREADS, 6) yolo_loss_kernel(
    const float*  __restrict__ feat,
    const float4* __restrict__ feat4,
    const float*  __restrict__ bboxes,
    const int*    __restrict__ labels,
    float* __restrict__ out,
    int n4,       // N*1470/4
    int M)        // N*GBOX
{
    const float CELL = 64.0f;
    const float INV_CELL = 1.0f / 64.0f;
    const float IMG = 448.0f;
    const float INV_IMG = 1.0f / 448.0f;

    float acc = 0.0f;

    if (blockIdx.x < GATHER_BLOCKS) {
        // ================= GATHER ROLE: one (n,g) per thread =================
        const int i = blockIdx.x * THREADS + threadIdx.x;
        if (i < M) {
            const int n = i >> 3;
            const float4 bb = __ldg((const float4*)(bboxes + (size_t)i * 4));
            const float x1 = bb.x, y1 = bb.y, x2 = bb.z, y2 = bb.w;

            const float cx = 0.5f * (x1 + x2);
            const float cy = 0.5f * (y1 + y2);
            const float gw = x2 - x1;
            const float gh = y2 - y1;

            int col = (int)floorf(cx * INV_CELL);
            int row = (int)floorf(cy * INV_CELL);
            col = min(S_GRID - 1, max(0, col));
            row = min(S_GRID - 1, max(0, row));

            const float2* cell2 = (const float2*)
                (feat + ((size_t)n * (S_GRID * S_GRID) + row * S_GRID + col) * D_FEAT);

            // box predictors: first 5 float2 (10 floats)
            const float2 q0 = __ldg(cell2 + 0);
            const float2 q1 = __ldg(cell2 + 1);
            const float2 q2 = __ldg(cell2 + 2);
            const float2 q3 = __ldg(cell2 + 3);
            const float2 q4 = __ldg(cell2 + 4);
            const float px0 = q0.x, py0 = q0.y, pw0 = q1.x, ph0 = q1.y, pc0 = q2.x;
            const float px1 = q2.y, py1 = q3.x, pw1 = q3.y, ph1 = q4.x, pc1 = q4.y;

            const float gx0 = (float)col * CELL;
            const float gy0 = (float)row * CELL;
            const float tx = cx * INV_CELL - (float)col;
            const float ty = cy * INV_CELL - (float)row;
            const float stw = sqrtf(gw * INV_IMG);
            const float sth = sqrtf(gh * INV_IMG);
            const float a2 = fmaxf(gw, 0.0f) * fmaxf(gh, 0.0f);

            float iou[2];
            const float pxs[2] = {px0, px1}, pys[2] = {py0, py1};
            const float pws[2] = {pw0, pw1}, phs[2] = {ph0, ph1};
            const float pcs[2] = {pc0, pc1};
            #pragma unroll
            for (int b = 0; b < 2; b++) {
                const float pcx = gx0 + pxs[b] * CELL;
                const float pcy = gy0 + pys[b] * CELL;
                const float pwa = pws[b] * IMG;
                const float pha = phs[b] * IMG;
                const float bx1 = pcx - 0.5f * pwa;
                const float by1 = pcy - 0.5f * pha;
                const float bx2 = pcx + 0.5f * pwa;
                const float by2 = pcy + 0.5f * pha;

                const float ix1 = fmaxf(bx1, x1);
                const float iy1 = fmaxf(by1, y1);
                const float ix2 = fminf(bx2, x2);
                const float iy2 = fminf(by2, y2);
                const float inter = fmaxf(ix2 - ix1, 0.0f) * fmaxf(iy2 - iy1, 0.0f);
                const float a1 = fmaxf(bx2 - bx1, 0.0f) * fmaxf(by2 - by1, 0.0f);
                iou[b] = inter / (a1 + a2 - inter + 1e-6f);
            }

            const int bi = (iou[1] > iou[0]) ? 1 : 0;  // first wins ties

            const float dpx = pxs[bi] - tx;
            const float dpy = pys[bi] - ty;
            const float dsw = sqrtf(fmaxf(pws[bi], 0.0f)) - stw;
            const float dsh = sqrtf(fmaxf(phs[bi], 0.0f)) - sth;
            acc += 5.0f * (dpx * dpx + dpy * dpy + dsw * dsw + dsh * dsh);

            const float dc = pcs[bi] - iou[bi];
            acc = fmaf(dc, dc, acc);
            acc = fmaf(-0.5f * pcs[bi], pcs[bi], acc);   // noobj correction

            // class loss: sum(clsp^2) - 2*clsp[lab] + 1, accumulated on the fly
            const int lab = __ldg(labels + i);
            float cls = 1.0f;
            float labv = 0.0f;
            #pragma unroll
            for (int k = 0; k < 10; k++) {
                const float2 v = __ldg(cell2 + 5 + k);
                cls = fmaf(v.x, v.x, cls);
                cls = fmaf(v.y, v.y, cls);
                const int c0 = 2 * k;
                if (lab == c0)     labv = v.x;
                if (lab == c0 + 1) labv = v.y;
            }
            acc += cls - 2.0f * labv;
        }
    } else {
        // ================= SWEEP ROLE: noobj base term =================
        // acc += 0.5 * conf^2 over all cells; conf elements are e%30 in {4,9}.
        // For float4 index j, row-local phase m = j % 15 (invariant: nth%15==0):
        //   m==1 -> .x (e=4)   m==2 -> .y (e=9)
        //   m==8 -> .z (e=4)   m==9 -> .w (e=9)
        const int sid = (blockIdx.x - GATHER_BLOCKS) * THREADS + threadIdx.x;
        const int nth = SWEEP_BLOCKS * THREADS;      // 491520, % 15 == 0
        const int m = sid % 15;
        const float mx = (m == 1) ? 1.0f : 0.0f;
        const float my = (m == 2) ? 1.0f : 0.0f;
        const float mz = (m == 8) ? 1.0f : 0.0f;
        const float mw = (m == 9) ? 1.0f : 0.0f;

        int j = sid;
        for (; j + 3 * nth < n4; j += 4 * nth) {
            const float4 v0 = __ldg(feat4 + j);
            const float4 v1 = __ldg(feat4 + j + nth);
            const float4 v2 = __ldg(feat4 + j + 2 * nth);
            const float4 v3 = __ldg(feat4 + j + 3 * nth);
            float c;
            c = v0.x * mx + v0.y * my + v0.z * mz + v0.w * mw;
            acc = fmaf(0.5f * c, c, acc);
            c = v1.x * mx + v1.y * my + v1.z * mz + v1.w * mw;
            acc = fmaf(0.5f * c, c, acc);
            c = v2.x * mx + v2.y * my + v2.z * mz + v2.w * mw;
            acc = fmaf(0.5f * c, c, acc);
            c = v3.x * mx + v3.y * my + v3.z * mz + v3.w * mw;
            acc = fmaf(0.5f * c, c, acc);
        }
        for (; j < n4; j += nth) {
            const float4 v = __ldg(feat4 + j);
            const float c = v.x * mx + v.y * my + v.z * mz + v.w * mw;
            acc = fmaf(0.5f * c, c, acc);
        }
    }

    // ---- Block reduction, one atomicAdd per block
    __shared__ float red[8];
    const int lane = threadIdx.x & 31;
    const int wid = threadIdx.x >> 5;
    #pragma unroll
    for (int off = 16; off > 0; off >>= 1)
        acc += __shfl_down_sync(0xFFFFFFFFu, acc, off);
    if (lane == 0) red[wid] = acc;
    __syncthreads();
    if (wid == 0) {
        float v = (lane < (THREADS >> 5)) ? red[lane] : 0.0f;
        #pragma unroll
        for (int off = 4; off > 0; off >>= 1)
            v += __shfl_down_sync(0xFFFFFFFFu, v, off);
        if (lane == 0) atomicAdd(out, v);
    }
}

extern "C" void kernel_launch(void* const* d_in, const int* in_sizes, int n_in,
                              void* d_out, int out_size) {
    const float* feat   = (const float*)d_in[0];
    const float* bboxes = (const float*)d_in[1];
    const int*   labels = (const int*)d_in[2];
    float* out = (float*)d_out;

    const int total = in_sizes[0];                       // N * 1470
    const int n4 = total / 4;
    const int N = total / (S_GRID * S_GRID * D_FEAT);    // 16384
    const int M = N * GBOX;

    init_out<<<1, 1>>>(out);
    yolo_loss_kernel<<<GATHER_BLOCKS + SWEEP_BLOCKS, THREADS>>>(
        feat, (const float4*)feat, bboxes, labels, out, n4, M);
}

// round 5
// speedup vs baseline: 2.2352x; 1.0789x over previous
#include <cuda_runtime.h>

// YOLOv1 loss — single-wave persistent kernel: per-thread gather (once),
// then grid-stride coalesced float4 sweep for the noobj term.
// S=7, B=2, C=20, D=30, CELL=64, IMG=448, LAMBDA_COORD=5, LAMBDA_NOOBJ=0.5

#define D_FEAT 30
#define S_GRID 7
#define GBOX 8
#define THREADS 256
#define NBLOCKS 870            // 15*58; 870 CTAs = single wave at 6 CTAs/SM
                               // nth = 222720, divisible by 15

__global__ void init_out(float* out) { out[0] = 0.0f; }

__global__ void __launch_bounds__(THREADS, 6) yolo_loss_kernel(
    const float*  __restrict__ feat,
    const float4* __restrict__ feat4,
    const float*  __restrict__ bboxes,
    const int*    __restrict__ labels,
    float* __restrict__ out,
    int n4,       // N*1470/4
    int M)        // N*GBOX
{
    const float CELL = 64.0f;
    const float INV_CELL = 1.0f / 64.0f;
    const float IMG = 448.0f;
    const float INV_IMG = 1.0f / 448.0f;

    const int tid = blockIdx.x * THREADS + threadIdx.x;
    const int nth = NBLOCKS * THREADS;      // 222720 ≡ 0 (mod 15)

    float acc = 0.0f;

    // ================= Phase 1: gather (one (n,g) per thread, tid < M) ======
    // Runs first: latency-bound burst + pre-warms gathered rows into L2.
    if (tid < M) {
        const int i = tid;
        const int n = i >> 3;
        const float4 bb = __ldg((const float4*)(bboxes + (size_t)i * 4));
        const float x1 = bb.x, y1 = bb.y, x2 = bb.z, y2 = bb.w;

        const float cx = 0.5f * (x1 + x2);
        const float cy = 0.5f * (y1 + y2);
        const float gw = x2 - x1;
        const float gh = y2 - y1;

        int col = (int)floorf(cx * INV_CELL);
        int row = (int)floorf(cy * INV_CELL);
        col = min(S_GRID - 1, max(0, col));
        row = min(S_GRID - 1, max(0, row));

        const float2* cell2 = (const float2*)
            (feat + ((size_t)n * (S_GRID * S_GRID) + row * S_GRID + col) * D_FEAT);

        const float2 q0 = __ldg(cell2 + 0);
        const float2 q1 = __ldg(cell2 + 1);
        const float2 q2 = __ldg(cell2 + 2);
        const float2 q3 = __ldg(cell2 + 3);
        const float2 q4 = __ldg(cell2 + 4);
        const float px0 = q0.x, py0 = q0.y, pw0 = q1.x, ph0 = q1.y, pc0 = q2.x;
        const float px1 = q2.y, py1 = q3.x, pw1 = q3.y, ph1 = q4.x, pc1 = q4.y;

        const float gx0 = (float)col * CELL;
        const float gy0 = (float)row * CELL;
        const float tx = cx * INV_CELL - (float)col;
        const float ty = cy * INV_CELL - (float)row;
        const float stw = sqrtf(gw * INV_IMG);
        const float sth = sqrtf(gh * INV_IMG);
        const float a2 = fmaxf(gw, 0.0f) * fmaxf(gh, 0.0f);

        float iou[2];
        const float pxs[2] = {px0, px1}, pys[2] = {py0, py1};
        const float pws[2] = {pw0, pw1}, phs[2] = {ph0, ph1};
        const float pcs[2] = {pc0, pc1};
        #pragma unroll
        for (int b = 0; b < 2; b++) {
            const float pcx = gx0 + pxs[b] * CELL;
            const float pcy = gy0 + pys[b] * CELL;
            const float pwa = pws[b] * IMG;
            const float pha = phs[b] * IMG;
            const float bx1 = pcx - 0.5f * pwa;
            const float by1 = pcy - 0.5f * pha;
            const float bx2 = pcx + 0.5f * pwa;
            const float by2 = pcy + 0.5f * pha;

            const float ix1 = fmaxf(bx1, x1);
            const float iy1 = fmaxf(by1, y1);
            const float ix2 = fminf(bx2, x2);
            const float iy2 = fminf(by2, y2);
            const float inter = fmaxf(ix2 - ix1, 0.0f) * fmaxf(iy2 - iy1, 0.0f);
            const float a1 = fmaxf(bx2 - bx1, 0.0f) * fmaxf(by2 - by1, 0.0f);
            iou[b] = inter / (a1 + a2 - inter + 1e-6f);
        }

        const int bi = (iou[1] > iou[0]) ? 1 : 0;  // first wins ties

        const float dpx = pxs[bi] - tx;
        const float dpy = pys[bi] - ty;
        const float dsw = sqrtf(fmaxf(pws[bi], 0.0f)) - stw;
        const float dsh = sqrtf(fmaxf(phs[bi], 0.0f)) - sth;
        acc += 5.0f * (dpx * dpx + dpy * dpy + dsw * dsw + dsh * dsh);

        const float dc = pcs[bi] - iou[bi];
        acc = fmaf(dc, dc, acc);
        acc = fmaf(-0.5f * pcs[bi], pcs[bi], acc);   // noobj correction

        const int lab = __ldg(labels + i);
        float cls = 1.0f;
        float labv = 0.0f;
        #pragma unroll
        for (int k = 0; k < 10; k++) {
            const float2 v = __ldg(cell2 + 5 + k);
            cls = fmaf(v.x, v.x, cls);
            cls = fmaf(v.y, v.y, cls);
            const int c0 = 2 * k;
            if (lab == c0)     labv = v.x;
            if (lab == c0 + 1) labv = v.y;
        }
        acc += cls - 2.0f * labv;
    }

    // ================= Phase 2: coalesced noobj sweep =======================
    // acc += 0.5 * conf^2, conf at e%30 in {4,9}. For float4 index j,
    // phase m = j % 15 is loop-invariant (nth % 15 == 0):
    //   m==1 -> .x   m==2 -> .y   m==8 -> .z   m==9 -> .w
    {
        const int m = tid % 15;
        const float mx = (m == 1) ? 1.0f : 0.0f;
        const float my = (m == 2) ? 1.0f : 0.0f;
        const float mz = (m == 8) ? 1.0f : 0.0f;
        const float mw = (m == 9) ? 1.0f : 0.0f;

        int j = tid;
        for (; j + 3 * nth < n4; j += 4 * nth) {
            const float4 v0 = __ldg(feat4 + j);
            const float4 v1 = __ldg(feat4 + j + nth);
            const float4 v2 = __ldg(feat4 + j + 2 * nth);
            const float4 v3 = __ldg(feat4 + j + 3 * nth);
            float c;
            c = v0.x * mx + v0.y * my + v0.z * mz + v0.w * mw;
            acc = fmaf(0.5f * c, c, acc);
            c = v1.x * mx + v1.y * my + v1.z * mz + v1.w * mw;
            acc = fmaf(0.5f * c, c, acc);
            c = v2.x * mx + v2.y * my + v2.z * mz + v2.w * mw;
            acc = fmaf(0.5f * c, c, acc);
            c = v3.x * mx + v3.y * my + v3.z * mz + v3.w * mw;
            acc = fmaf(0.5f * c, c, acc);
        }
        for (; j < n4; j += nth) {
            const float4 v = __ldg(feat4 + j);
            const float c = v.x * mx + v.y * my + v.z * mz + v.w * mw;
            acc = fmaf(0.5f * c, c, acc);
        }
    }

    // ---- Block reduction, one atomicAdd per block
    __shared__ float red[8];
    const int lane = threadIdx.x & 31;
    const int wid = threadIdx.x >> 5;
    #pragma unroll
    for (int off = 16; off > 0; off >>= 1)
        acc += __shfl_down_sync(0xFFFFFFFFu, acc, off);
    if (lane == 0) red[wid] = acc;
    __syncthreads();
    if (wid == 0) {
        float v = (lane < (THREADS >> 5)) ? red[lane] : 0.0f;
        #pragma unroll
        for (int off = 4; off > 0; off >>= 1)
            v += __shfl_down_sync(0xFFFFFFFFu, v, off);
        if (lane == 0) atomicAdd(out, v);
    }
}

extern "C" void kernel_launch(void* const* d_in, const int* in_sizes, int n_in,
                              void* d_out, int out_size) {
    const float* feat   = (const float*)d_in[0];
    const float* bboxes = (const float*)d_in[1];
    const int*   labels = (const int*)d_in[2];
    float* out = (float*)d_out;

    const int total = in_sizes[0];                       // N * 1470
    const int n4 = total / 4;
    const int N = total / (S_GRID * S_GRID * D_FEAT);    // 16384
    const int M = N * GBOX;

    init_out<<<1, 1>>>(out);
    yolo_loss_kernel<<<NBLOCKS, THREADS>>>(feat, (const float4*)feat,
                                           bboxes, labels, out, n4, M);
}